// round 2
// baseline (speedup 1.0000x reference)
#include <cuda_runtime.h>

#define NNODES 100000
#define NEDGES 3200000
#define NREL   8
#define CIN    128
#define HID    64
#define YCOLS  576      // 512 relation columns + 64 root columns
#define RELCOLS 512

// ---------------- scratch (device globals: no allocation allowed) ----------
__device__ float g_Y[(size_t)NNODES * YCOLS];   // GEMM output, reused both layers (230 MB)
__device__ float g_h[(size_t)NNODES * HID];     // layer-1 activations (25.6 MB)
__device__ float g_Wp[CIN * YCOLS];             // packed weights (reused per layer)
__device__ int   g_cnt[NREL * NNODES];          // per-(relation,dst) in-degree
__device__ int   g_rowptr[NNODES + 1];          // CSR row pointers (dst-keyed)
__device__ int   g_cursor[NNODES];              // scatter cursors
__device__ int   g_bsums[256];                  // scan partials
__device__ int2  g_emeta[NEDGES];               // {gather offset, 1/deg as bits}

// ---------------- CSR build --------------------------------------------------
__global__ void k_zero_cnt() {
    int i = blockIdx.x * blockDim.x + threadIdx.x;
    if (i < NREL * NNODES) g_cnt[i] = 0;
}

__global__ void k_count(const int* __restrict__ dst, const int* __restrict__ et) {
    int e = blockIdx.x * blockDim.x + threadIdx.x;
    if (e < NEDGES) atomicAdd(&g_cnt[et[e] * NNODES + dst[e]], 1);
}

// block-level exclusive scan of per-node totals (sum over relations)
__global__ void k_scan1() {
    __shared__ int sh[1024];
    int d = blockIdx.x * 1024 + threadIdx.x;
    int tot = 0;
    if (d < NNODES) {
#pragma unroll
        for (int r = 0; r < NREL; r++) tot += g_cnt[r * NNODES + d];
    }
    sh[threadIdx.x] = tot;
    __syncthreads();
    for (int off = 1; off < 1024; off <<= 1) {
        int v = 0;
        if (threadIdx.x >= off) v = sh[threadIdx.x - off];
        __syncthreads();
        sh[threadIdx.x] += v;
        __syncthreads();
    }
    if (d < NNODES) g_rowptr[d] = sh[threadIdx.x] - tot;  // exclusive
    if (threadIdx.x == 1023) g_bsums[blockIdx.x] = sh[1023];
}

__global__ void k_scan2(int nb) {
    if (threadIdx.x == 0 && blockIdx.x == 0) {
        int run = 0;
        for (int i = 0; i < nb; i++) { int v = g_bsums[i]; g_bsums[i] = run; run += v; }
    }
}

__global__ void k_scan3() {
    int d = blockIdx.x * blockDim.x + threadIdx.x;
    if (d < NNODES) {
        int v = g_rowptr[d] + g_bsums[d >> 10];
        g_rowptr[d] = v;
        g_cursor[d] = v;
    }
    if (d == 0) g_rowptr[NNODES] = NEDGES;
}

__global__ void k_scatter(const int* __restrict__ src, const int* __restrict__ dst,
                          const int* __restrict__ et) {
    int e = blockIdx.x * blockDim.x + threadIdx.x;
    if (e >= NEDGES) return;
    int s = src[e], d = dst[e], r = et[e];
    int pos = atomicAdd(&g_cursor[d], 1);
    float sc = 1.0f / (float)g_cnt[r * NNODES + d];   // count >= 1 for an existing edge
    g_emeta[pos] = make_int2(s * YCOLS + r * HID, __float_as_int(sc));
}

// ---------------- weight packing: Wp[k][r*64+h] = W[r][k][h]; Wp[k][512+h]=root[k][h]
__global__ void k_pack(const float* __restrict__ W, const float* __restrict__ root, int K) {
    int i = blockIdx.x * blockDim.x + threadIdx.x;
    if (i >= K * YCOLS) return;
    int k = i / YCOLS, j = i % YCOLS;
    float v;
    if (j < RELCOLS) {
        int r = j >> 6, h = j & 63;
        v = W[(r * K + k) * HID + h];
    } else {
        v = root[k * HID + (j - RELCOLS)];
    }
    g_Wp[i] = v;
}

// ---------------- GEMM: g_Y[m, 0:576] = X[m, 0:K] @ g_Wp ------------------
#define BM 128
#define BN 64
#define BK 16
#define TM 8
#define TN 4

__global__ void __launch_bounds__(256) k_gemm(const float* __restrict__ Xext, int K, int useH) {
    __shared__ float As[BK][BM + 4];
    __shared__ float Bs[BK][BN];

    const float* __restrict__ X = useH ? (const float*)g_h : Xext;

    int tid  = threadIdx.x;
    int row0 = blockIdx.y * BM;
    int col0 = blockIdx.x * BN;

    int tx = tid & 15;   // output column group
    int ty = tid >> 4;   // output row group

    float acc[TM][TN];
#pragma unroll
    for (int i = 0; i < TM; i++)
#pragma unroll
        for (int j = 0; j < TN; j++) acc[i][j] = 0.f;

    int ar = tid >> 2;          // 0..63
    int ak = (tid & 3) * 4;     // 0,4,8,12
    int bk = tid >> 4;          // 0..15
    int bc = (tid & 15) * 4;    // 0..60

    for (int k0 = 0; k0 < K; k0 += BK) {
#pragma unroll
        for (int half = 0; half < 2; half++) {
            int r = row0 + ar + half * 64;
            float4 v = make_float4(0.f, 0.f, 0.f, 0.f);
            if (r < NNODES) v = *(const float4*)(X + (size_t)r * K + k0 + ak);
            As[ak + 0][ar + half * 64] = v.x;
            As[ak + 1][ar + half * 64] = v.y;
            As[ak + 2][ar + half * 64] = v.z;
            As[ak + 3][ar + half * 64] = v.w;
        }
        {
            float4 v = *(const float4*)(g_Wp + (size_t)(k0 + bk) * YCOLS + col0 + bc);
            *(float4*)&Bs[bk][bc] = v;
        }
        __syncthreads();
#pragma unroll
        for (int kk = 0; kk < BK; kk++) {
            float a[TM], b[TN];
#pragma unroll
            for (int i = 0; i < TM; i++) a[i] = As[kk][ty * TM + i];
#pragma unroll
            for (int j = 0; j < TN; j++) b[j] = Bs[kk][tx * TN + j];
#pragma unroll
            for (int i = 0; i < TM; i++)
#pragma unroll
                for (int j = 0; j < TN; j++) acc[i][j] = fmaf(a[i], b[j], acc[i][j]);
        }
        __syncthreads();
    }
#pragma unroll
    for (int i = 0; i < TM; i++) {
        int r = row0 + ty * TM + i;
        if (r < NNODES) {
            float4 v = make_float4(acc[i][0], acc[i][1], acc[i][2], acc[i][3]);
            *(float4*)(g_Y + (size_t)r * YCOLS + col0 + tx * TN) = v;
        }
    }
}

// ---------------- aggregation: one warp per destination node ----------------
// out[d] = (relu?)( sum_edges Y[off + h]*scale + Y[d*576+512+h] (root) + bias[h] )
__global__ void __launch_bounds__(256) k_agg(const float* __restrict__ bias,
                                             float* __restrict__ outext, int mode /*1=layer1*/) {
    int warp = (blockIdx.x * blockDim.x + threadIdx.x) >> 5;
    int lane = threadIdx.x & 31;
    if (warp >= NNODES) return;

    float* __restrict__ out = mode ? (float*)g_h : outext;

    int start = g_rowptr[warp];
    int end   = g_rowptr[warp + 1];

    float ax = 0.f, ay = 0.f;
    int e = start;
    for (; e + 4 <= end; e += 4) {
        int2 m0 = g_emeta[e + 0];
        int2 m1 = g_emeta[e + 1];
        int2 m2 = g_emeta[e + 2];
        int2 m3 = g_emeta[e + 3];
        float2 v0 = *(const float2*)(g_Y + m0.x + lane * 2);
        float2 v1 = *(const float2*)(g_Y + m1.x + lane * 2);
        float2 v2 = *(const float2*)(g_Y + m2.x + lane * 2);
        float2 v3 = *(const float2*)(g_Y + m3.x + lane * 2);
        float s0 = __int_as_float(m0.y), s1 = __int_as_float(m1.y);
        float s2 = __int_as_float(m2.y), s3 = __int_as_float(m3.y);
        ax = fmaf(v0.x, s0, ax); ay = fmaf(v0.y, s0, ay);
        ax = fmaf(v1.x, s1, ax); ay = fmaf(v1.y, s1, ay);
        ax = fmaf(v2.x, s2, ax); ay = fmaf(v2.y, s2, ay);
        ax = fmaf(v3.x, s3, ax); ay = fmaf(v3.y, s3, ay);
    }
    for (; e < end; e++) {
        int2 m = g_emeta[e];
        float2 v = *(const float2*)(g_Y + m.x + lane * 2);
        float s = __int_as_float(m.y);
        ax = fmaf(v.x, s, ax); ay = fmaf(v.y, s, ay);
    }

    const float* base = g_Y + (size_t)warp * YCOLS + RELCOLS;
    float bx = ax + base[lane * 2 + 0] + bias[lane * 2 + 0];
    float by = ay + base[lane * 2 + 1] + bias[lane * 2 + 1];
    if (mode) { bx = fmaxf(bx, 0.f); by = fmaxf(by, 0.f); }
    *(float2*)(out + (size_t)warp * HID + lane * 2) = make_float2(bx, by);
}

// ---------------- launch ----------------------------------------------------
extern "C" void kernel_launch(void* const* d_in, const int* in_sizes, int n_in,
                              void* d_out, int out_size) {
    const float* x     = (const float*)d_in[0];
    const int*   ei    = (const int*)d_in[1];
    const int*   et    = (const int*)d_in[2];
    const float* W1    = (const float*)d_in[3];
    const float* root1 = (const float*)d_in[4];
    const float* b1    = (const float*)d_in[5];
    const float* W2    = (const float*)d_in[6];
    const float* root2 = (const float*)d_in[7];
    const float* b2    = (const float*)d_in[8];
    float* out = (float*)d_out;

    const int* src = ei;            // edge_index[0]
    const int* dst = ei + NEDGES;   // edge_index[1]

    // CSR + degrees (shared by both layers)
    k_zero_cnt<<<(NREL * NNODES + 255) / 256, 256>>>();
    k_count<<<(NEDGES + 255) / 256, 256>>>(dst, et);
    int nb = (NNODES + 1023) / 1024;
    k_scan1<<<nb, 1024>>>();
    k_scan2<<<1, 32>>>(nb);
    k_scan3<<<(NNODES + 255) / 256, 256>>>();
    k_scatter<<<(NEDGES + 255) / 256, 256>>>(src, dst, et);

    dim3 ggrid(YCOLS / BN, (NNODES + BM - 1) / BM);
    int agrid = (NNODES * 32 + 255) / 256;

    // layer 1: Y = x @ [W1|root1]; h = relu(agg + root + b1)
    k_pack<<<(CIN * YCOLS + 255) / 256, 256>>>(W1, root1, CIN);
    k_gemm<<<ggrid, 256>>>(x, CIN, 0);
    k_agg<<<agrid, 256>>>(b1, nullptr, 1);

    // layer 2: Y = h @ [W2|root2]; out = agg + root + b2
    k_pack<<<(HID * YCOLS + 255) / 256, 256>>>(W2, root2, HID);
    k_gemm<<<ggrid, 256>>>(nullptr, HID, 1);
    k_agg<<<agrid, 256>>>(b2, out, 0);
}

// round 4
// speedup vs baseline: 1.3959x; 1.3959x over previous
#include <cuda_runtime.h>
#include <cuda_bf16.h>
#include <cstdint>

#define NNODES 100000
#define NEDGES 3200000
#define NREL   8
#define CIN    128
#define HID    64
#define YCOLS  576
#define RELCOLS 512

// ---------------- scratch ----------------------------------------------------
__device__ float g_Y[(size_t)NNODES * YCOLS];
__device__ __align__(16) float g_h[(size_t)NNODES * HID];
__device__ __align__(16) __nv_bfloat16 g_Wh[YCOLS * CIN];   // [col][k], k-contig
__device__ __align__(16) __nv_bfloat16 g_Wl[YCOLS * CIN];
__device__ int   g_cnt[NREL * NNODES];
__device__ int   g_rowptr[NNODES + 1];
__device__ int   g_cursor[NNODES];
__device__ int   g_bsums[256];
__device__ int2  g_emeta[NEDGES];

// ---------------- CSR build (unchanged from passing R1 kernel) ---------------
__global__ void k_zero_cnt() {
    int i = blockIdx.x * blockDim.x + threadIdx.x;
    if (i < NREL * NNODES) g_cnt[i] = 0;
}
__global__ void k_count(const int* __restrict__ dst, const int* __restrict__ et) {
    int e = blockIdx.x * blockDim.x + threadIdx.x;
    if (e < NEDGES) atomicAdd(&g_cnt[et[e] * NNODES + dst[e]], 1);
}
__global__ void k_scan1() {
    __shared__ int sh[1024];
    int d = blockIdx.x * 1024 + threadIdx.x;
    int tot = 0;
    if (d < NNODES) {
#pragma unroll
        for (int r = 0; r < NREL; r++) tot += g_cnt[r * NNODES + d];
    }
    sh[threadIdx.x] = tot;
    __syncthreads();
    for (int off = 1; off < 1024; off <<= 1) {
        int v = 0;
        if (threadIdx.x >= off) v = sh[threadIdx.x - off];
        __syncthreads();
        sh[threadIdx.x] += v;
        __syncthreads();
    }
    if (d < NNODES) g_rowptr[d] = sh[threadIdx.x] - tot;
    if (threadIdx.x == 1023) g_bsums[blockIdx.x] = sh[1023];
}
__global__ void k_scan2(int nb) {
    if (threadIdx.x == 0 && blockIdx.x == 0) {
        int run = 0;
        for (int i = 0; i < nb; i++) { int v = g_bsums[i]; g_bsums[i] = run; run += v; }
    }
}
__global__ void k_scan3() {
    int d = blockIdx.x * blockDim.x + threadIdx.x;
    if (d < NNODES) {
        int v = g_rowptr[d] + g_bsums[d >> 10];
        g_rowptr[d] = v;
        g_cursor[d] = v;
    }
    if (d == 0) g_rowptr[NNODES] = NEDGES;
}
__global__ void k_scatter(const int* __restrict__ src, const int* __restrict__ dst,
                          const int* __restrict__ et) {
    int e = blockIdx.x * blockDim.x + threadIdx.x;
    if (e >= NEDGES) return;
    int s = src[e], d = dst[e], r = et[e];
    int pos = atomicAdd(&g_cursor[d], 1);
    float sc = 1.0f / (float)g_cnt[r * NNODES + d];
    g_emeta[pos] = make_int2(s * YCOLS + r * HID, __float_as_int(sc));
}

// ---------------- weight pack: bf16 hi/lo, [col][k] layout -------------------
__global__ void k_pack(const float* __restrict__ W, const float* __restrict__ root, int K) {
    int i = blockIdx.x * blockDim.x + threadIdx.x;
    if (i >= K * YCOLS) return;
    int j = i / K, k = i % K;
    float v;
    if (j < RELCOLS) {
        int r = j >> 6, h = j & 63;
        v = W[((size_t)r * K + k) * HID + h];
    } else {
        v = root[(size_t)k * HID + (j - RELCOLS)];
    }
    __nv_bfloat16 hi = __float2bfloat16(v);
    float lo = v - __bfloat162float(hi);
    g_Wh[i] = hi;
    g_Wl[i] = __float2bfloat16(lo);
}

// ---------------- mma.sync GEMM ----------------------------------------------
__device__ __forceinline__ uint32_t smem_u32(const void* p) {
    uint32_t a;
    asm("{ .reg .u64 t; cvta.to.shared.u64 t, %1; cvt.u32.u64 %0, t; }" : "=r"(a) : "l"(p));
    return a;
}
__device__ __forceinline__ void ldm4(uint32_t* r, uint32_t addr) {
    asm volatile("ldmatrix.sync.aligned.m8n8.x4.shared.b16 {%0,%1,%2,%3}, [%4];"
                 : "=r"(r[0]), "=r"(r[1]), "=r"(r[2]), "=r"(r[3]) : "r"(addr));
}
__device__ __forceinline__ void mma16816(float* d, const uint32_t* a, uint32_t b0, uint32_t b1) {
    asm volatile(
        "mma.sync.aligned.m16n8k16.row.col.f32.bf16.bf16.f32 "
        "{%0,%1,%2,%3}, {%4,%5,%6,%7}, {%8,%9}, {%0,%1,%2,%3};"
        : "+f"(d[0]), "+f"(d[1]), "+f"(d[2]), "+f"(d[3])
        : "r"(a[0]), "r"(a[1]), "r"(a[2]), "r"(a[3]), "r"(b0), "r"(b1));
}

// Y[128 rows x 576] = X[128 x K] @ Wp^T   (Wp stored [col][k])
// split precision: acc = Ah*Bh + Ah*Bl + Al*Bh, fp32 accumulators.
__global__ void __launch_bounds__(256, 2) k_gemm_mma(const float* __restrict__ Xext,
                                                     int K, int useH) {
    extern __shared__ char smem[];
    const float* __restrict__ X = useH ? (const float*)g_h : Xext;
    const int RB = K * 2;                 // bytes per smem row
    const int OFF_AH = 0;
    const int OFF_AL = 128 * RB;
    const int OFF_BH = 256 * RB;
    const int OFF_BL = 320 * RB;
    uint32_t sb = smem_u32(smem);

    int tid = threadIdx.x, wid = tid >> 5, lane = tid & 31;
    int row0 = blockIdx.x * 128;
    int KQ = K >> 2;

    // ---- load A (128 x K fp32), split to bf16 hi/lo, swizzled store ----
    for (int q = tid; q < 128 * KQ; q += 256) {
        int row = q / KQ, k = (q % KQ) * 4;
        float4 v = make_float4(0.f, 0.f, 0.f, 0.f);
        int rg = row0 + row;
        if (rg < NNODES) v = *(const float4*)(X + (size_t)rg * K + k);
        __nv_bfloat16 h0 = __float2bfloat16(v.x), h1 = __float2bfloat16(v.y);
        __nv_bfloat16 h2 = __float2bfloat16(v.z), h3 = __float2bfloat16(v.w);
        __nv_bfloat16 l0 = __float2bfloat16(v.x - __bfloat162float(h0));
        __nv_bfloat16 l1 = __float2bfloat16(v.y - __bfloat162float(h1));
        __nv_bfloat16 l2 = __float2bfloat16(v.z - __bfloat162float(h2));
        __nv_bfloat16 l3 = __float2bfloat16(v.w - __bfloat162float(h3));
        uint2 hp, lp;
        hp.x = ((uint32_t)__bfloat16_as_ushort(h1) << 16) | __bfloat16_as_ushort(h0);
        hp.y = ((uint32_t)__bfloat16_as_ushort(h3) << 16) | __bfloat16_as_ushort(h2);
        lp.x = ((uint32_t)__bfloat16_as_ushort(l1) << 16) | __bfloat16_as_ushort(l0);
        lp.y = ((uint32_t)__bfloat16_as_ushort(l3) << 16) | __bfloat16_as_ushort(l2);
        int chunk = (k >> 3) ^ (row & 7);
        int off = row * RB + chunk * 16 + (k & 7) * 2;
        *(uint2*)(smem + OFF_AH + off) = hp;
        *(uint2*)(smem + OFF_AL + off) = lp;
    }
    __syncthreads();

    // warp tiling: 4 row groups x 2 col groups of m32n32
    int wrow = (wid >> 1) * 32;
    int wcol = (wid & 1) * 32;
    int CPR = K >> 3;   // 16B chunks per row

    for (int nb = 0; nb < 9; nb++) {
        int col0 = nb * 64;
        // ---- load B chunk (64 cols x K), hi/lo, swizzled ----
        for (int q = tid; q < 64 * CPR; q += 256) {
            int n = q / CPR, kc = q % CPR;
            size_t gsrc = (size_t)(col0 + n) * K + kc * 8;
            int off = n * RB + ((kc ^ (n & 7)) * 16);
            *(uint4*)(smem + OFF_BH + off) = *(const uint4*)(g_Wh + gsrc);
            *(uint4*)(smem + OFF_BL + off) = *(const uint4*)(g_Wl + gsrc);
        }
        __syncthreads();

        float acc[2][4][4];
#pragma unroll
        for (int mt = 0; mt < 2; mt++)
#pragma unroll
            for (int nt = 0; nt < 4; nt++)
#pragma unroll
                for (int j = 0; j < 4; j++) acc[mt][nt][j] = 0.f;

        // precompute per-lane ldmatrix row bases
        // A frags: row = wrow + mt*16 + (lane&7) + ((lane>>3)&1)*8 ; k chunk += (lane>>4)
        int arow[2], as[2];
#pragma unroll
        for (int mt = 0; mt < 2; mt++) {
            int r = wrow + mt * 16 + (lane & 7) + ((lane >> 3) & 1) * 8;
            arow[mt] = r * RB;
            as[mt] = r & 7;
        }
        int akc = lane >> 4;                 // +0 or +1 chunk (k+8)
        // B frags: n = wcol + nt2*16 + (lane&7) + (lane>>4)*8 ; k chunk += ((lane>>3)&1)
        int brow[2], bs[2];
#pragma unroll
        for (int nt2 = 0; nt2 < 2; nt2++) {
            int n = wcol + nt2 * 16 + (lane & 7) + (lane >> 4) * 8;
            brow[nt2] = n * RB;
            bs[nt2] = n & 7;
        }
        int bkc = (lane >> 3) & 1;

        int nkstep = K >> 4;
        for (int ks = 0; ks < nkstep; ks++) {
            int kc0 = ks * 2;
            uint32_t ah[2][4], al[2][4], bh[2][4], bl[2][4];
#pragma unroll
            for (int mt = 0; mt < 2; mt++) {
                uint32_t off = arow[mt] + (uint32_t)(((kc0 + akc) ^ as[mt]) * 16);
                ldm4(ah[mt], sb + OFF_AH + off);
                ldm4(al[mt], sb + OFF_AL + off);
            }
#pragma unroll
            for (int nt2 = 0; nt2 < 2; nt2++) {
                uint32_t off = brow[nt2] + (uint32_t)(((kc0 + bkc) ^ bs[nt2]) * 16);
                ldm4(bh[nt2], sb + OFF_BH + off);
                ldm4(bl[nt2], sb + OFF_BL + off);
            }
#pragma unroll
            for (int mt = 0; mt < 2; mt++) {
#pragma unroll
                for (int nt = 0; nt < 4; nt++) {
                    uint32_t b0h = bh[nt >> 1][(nt & 1) * 2], b1h = bh[nt >> 1][(nt & 1) * 2 + 1];
                    uint32_t b0l = bl[nt >> 1][(nt & 1) * 2], b1l = bl[nt >> 1][(nt & 1) * 2 + 1];
                    mma16816(acc[mt][nt], ah[mt], b0h, b1h);
                    mma16816(acc[mt][nt], ah[mt], b0l, b1l);
                    mma16816(acc[mt][nt], al[mt], b0h, b1h);
                }
            }
        }

        // ---- epilogue: write 128x64 fp32 tile ----
#pragma unroll
        for (int mt = 0; mt < 2; mt++) {
            int r0 = row0 + wrow + mt * 16 + (lane >> 2);
#pragma unroll
            for (int nt = 0; nt < 4; nt++) {
                int c = col0 + wcol + nt * 8 + (lane & 3) * 2;
                if (r0 < NNODES)
                    *(float2*)(g_Y + (size_t)r0 * YCOLS + c) =
                        make_float2(acc[mt][nt][0], acc[mt][nt][1]);
                if (r0 + 8 < NNODES)
                    *(float2*)(g_Y + (size_t)(r0 + 8) * YCOLS + c) =
                        make_float2(acc[mt][nt][2], acc[mt][nt][3]);
            }
        }
        __syncthreads();
    }
}

// ---------------- aggregation (unchanged) ------------------------------------
__global__ void __launch_bounds__(256) k_agg(const float* __restrict__ bias,
                                             float* __restrict__ outext, int mode) {
    int warp = (blockIdx.x * blockDim.x + threadIdx.x) >> 5;
    int lane = threadIdx.x & 31;
    if (warp >= NNODES) return;
    float* __restrict__ out = mode ? (float*)g_h : outext;
    int start = g_rowptr[warp];
    int end   = g_rowptr[warp + 1];
    float ax = 0.f, ay = 0.f;
    int e = start;
    for (; e + 4 <= end; e += 4) {
        int2 m0 = g_emeta[e + 0], m1 = g_emeta[e + 1];
        int2 m2 = g_emeta[e + 2], m3 = g_emeta[e + 3];
        float2 v0 = *(const float2*)(g_Y + m0.x + lane * 2);
        float2 v1 = *(const float2*)(g_Y + m1.x + lane * 2);
        float2 v2 = *(const float2*)(g_Y + m2.x + lane * 2);
        float2 v3 = *(const float2*)(g_Y + m3.x + lane * 2);
        float s0 = __int_as_float(m0.y), s1 = __int_as_float(m1.y);
        float s2 = __int_as_float(m2.y), s3 = __int_as_float(m3.y);
        ax = fmaf(v0.x, s0, ax); ay = fmaf(v0.y, s0, ay);
        ax = fmaf(v1.x, s1, ax); ay = fmaf(v1.y, s1, ay);
        ax = fmaf(v2.x, s2, ax); ay = fmaf(v2.y, s2, ay);
        ax = fmaf(v3.x, s3, ax); ay = fmaf(v3.y, s3, ay);
    }
    for (; e < end; e++) {
        int2 m = g_emeta[e];
        float2 v = *(const float2*)(g_Y + m.x + lane * 2);
        float s = __int_as_float(m.y);
        ax = fmaf(v.x, s, ax); ay = fmaf(v.y, s, ay);
    }
    const float* base = g_Y + (size_t)warp * YCOLS + RELCOLS;
    float bx = ax + base[lane * 2 + 0] + bias[lane * 2 + 0];
    float by = ay + base[lane * 2 + 1] + bias[lane * 2 + 1];
    if (mode) { bx = fmaxf(bx, 0.f); by = fmaxf(by, 0.f); }
    *(float2*)(out + (size_t)warp * HID + lane * 2) = make_float2(bx, by);
}

// ---------------- launch ------------------------------------------------------
extern "C" void kernel_launch(void* const* d_in, const int* in_sizes, int n_in,
                              void* d_out, int out_size) {
    const float* x     = (const float*)d_in[0];
    const int*   ei    = (const int*)d_in[1];
    const int*   et    = (const int*)d_in[2];
    const float* W1    = (const float*)d_in[3];
    const float* root1 = (const float*)d_in[4];
    const float* b1    = (const float*)d_in[5];
    const float* W2    = (const float*)d_in[6];
    const float* root2 = (const float*)d_in[7];
    const float* b2    = (const float*)d_in[8];
    float* out = (float*)d_out;

    const int* src = ei;
    const int* dst = ei + NEDGES;

    static int smem_set = 0;
    if (!smem_set) {
        cudaFuncSetAttribute(k_gemm_mma, cudaFuncAttributeMaxDynamicSharedMemorySize,
                             384 * CIN * 2);
        smem_set = 1;
    }

    // CSR + degrees (shared by both layers)
    k_zero_cnt<<<(NREL * NNODES + 255) / 256, 256>>>();
    k_count<<<(NEDGES + 255) / 256, 256>>>(dst, et);
    int nb = (NNODES + 1023) / 1024;
    k_scan1<<<nb, 1024>>>();
    k_scan2<<<1, 32>>>(nb);
    k_scan3<<<(NNODES + 255) / 256, 256>>>();
    k_scatter<<<(NEDGES + 255) / 256, 256>>>(src, dst, et);

    int ggrid = (NNODES + 127) / 128;
    int agrid = (NNODES * 32 + 255) / 256;

    // layer 1
    k_pack<<<(CIN * YCOLS + 255) / 256, 256>>>(W1, root1, CIN);
    k_gemm_mma<<<ggrid, 256, 384 * CIN * 2>>>(x, CIN, 0);
    k_agg<<<agrid, 256>>>(b1, nullptr, 1);

    // layer 2
    k_pack<<<(HID * YCOLS + 255) / 256, 256>>>(W2, root2, HID);
    k_gemm_mma<<<ggrid, 256, 384 * HID * 2>>>(nullptr, HID, 1);
    k_agg<<<agrid, 256>>>(b2, out, 0);
}

// round 5
// speedup vs baseline: 1.8099x; 1.2966x over previous
#include <cuda_runtime.h>
#include <cuda_bf16.h>
#include <cuda_fp16.h>
#include <cstdint>

#define NNODES 100000
#define NEDGES 3200000
#define NREL   8
#define CIN    128
#define HID    64
#define RELCOLS 512

// ---------------- scratch ----------------------------------------------------
__device__ __align__(16) __half g_Ym[(size_t)NNODES * RELCOLS];   // relation msgs, fp16 (102 MB)
__device__ __align__(16) float  g_Yroot[(size_t)NNODES * HID];    // root part, fp32
__device__ __align__(16) float  g_h[(size_t)NNODES * HID];
__device__ __align__(16) __nv_bfloat16 g_Wh[(RELCOLS + HID) * CIN];  // [col][k]
__device__ __align__(16) __nv_bfloat16 g_Wl[(RELCOLS + HID) * CIN];
__device__ int   g_cnt[NREL * NNODES];
__device__ int   g_rowptr[NNODES + 1];
__device__ int   g_cursor[NNODES];
__device__ int   g_bsums[256];
__device__ int2  g_emeta[NEDGES];

#define YCOLS (RELCOLS + HID)

// ---------------- CSR build --------------------------------------------------
__global__ void k_zero_cnt() {
    int i = blockIdx.x * blockDim.x + threadIdx.x;
    if (i < NREL * NNODES) g_cnt[i] = 0;
}
__global__ void k_count(const int* __restrict__ dst, const int* __restrict__ et) {
    int e = blockIdx.x * blockDim.x + threadIdx.x;
    if (e < NEDGES) atomicAdd(&g_cnt[et[e] * NNODES + dst[e]], 1);
}
__global__ void k_scan1() {
    __shared__ int sh[1024];
    int d = blockIdx.x * 1024 + threadIdx.x;
    int tot = 0;
    if (d < NNODES) {
#pragma unroll
        for (int r = 0; r < NREL; r++) tot += g_cnt[r * NNODES + d];
    }
    sh[threadIdx.x] = tot;
    __syncthreads();
    for (int off = 1; off < 1024; off <<= 1) {
        int v = 0;
        if (threadIdx.x >= off) v = sh[threadIdx.x - off];
        __syncthreads();
        sh[threadIdx.x] += v;
        __syncthreads();
    }
    if (d < NNODES) g_rowptr[d] = sh[threadIdx.x] - tot;
    if (threadIdx.x == 1023) g_bsums[blockIdx.x] = sh[1023];
}
__global__ void k_scan2(int nb) {
    if (threadIdx.x == 0 && blockIdx.x == 0) {
        int run = 0;
        for (int i = 0; i < nb; i++) { int v = g_bsums[i]; g_bsums[i] = run; run += v; }
    }
}
__global__ void k_scan3() {
    int d = blockIdx.x * blockDim.x + threadIdx.x;
    if (d < NNODES) {
        int v = g_rowptr[d] + g_bsums[d >> 10];
        g_rowptr[d] = v;
        g_cursor[d] = v;
    }
    if (d == 0) g_rowptr[NNODES] = NEDGES;
}
__global__ void k_scatter(const int* __restrict__ src, const int* __restrict__ dst,
                          const int* __restrict__ et) {
    int e = blockIdx.x * blockDim.x + threadIdx.x;
    if (e >= NEDGES) return;
    int s = src[e], d = dst[e], r = et[e];
    int pos = atomicAdd(&g_cursor[d], 1);
    float sc = 1.0f / (float)g_cnt[r * NNODES + d];
    g_emeta[pos] = make_int2(s * RELCOLS + r * HID, __float_as_int(sc));  // half-index
}

// ---------------- weight pack ------------------------------------------------
__global__ void k_pack(const float* __restrict__ W, const float* __restrict__ root, int K) {
    int i = blockIdx.x * blockDim.x + threadIdx.x;
    if (i >= K * YCOLS) return;
    int j = i / K, k = i % K;
    float v;
    if (j < RELCOLS) {
        int r = j >> 6, h = j & 63;
        v = W[((size_t)r * K + k) * HID + h];
    } else {
        v = root[(size_t)k * HID + (j - RELCOLS)];
    }
    __nv_bfloat16 hi = __float2bfloat16(v);
    float lo = v - __bfloat162float(hi);
    g_Wh[i] = hi;
    g_Wl[i] = __float2bfloat16(lo);
}

// ---------------- mma.sync GEMM ----------------------------------------------
__device__ __forceinline__ uint32_t smem_u32(const void* p) {
    uint32_t a;
    asm("{ .reg .u64 t; cvta.to.shared.u64 t, %1; cvt.u32.u64 %0, t; }" : "=r"(a) : "l"(p));
    return a;
}
__device__ __forceinline__ void ldm4(uint32_t* r, uint32_t addr) {
    asm volatile("ldmatrix.sync.aligned.m8n8.x4.shared.b16 {%0,%1,%2,%3}, [%4];"
                 : "=r"(r[0]), "=r"(r[1]), "=r"(r[2]), "=r"(r[3]) : "r"(addr));
}
__device__ __forceinline__ void mma16816(float* d, const uint32_t* a, uint32_t b0, uint32_t b1) {
    asm volatile(
        "mma.sync.aligned.m16n8k16.row.col.f32.bf16.bf16.f32 "
        "{%0,%1,%2,%3}, {%4,%5,%6,%7}, {%8,%9}, {%0,%1,%2,%3};"
        : "+f"(d[0]), "+f"(d[1]), "+f"(d[2]), "+f"(d[3])
        : "r"(a[0]), "r"(a[1]), "r"(a[2]), "r"(a[3]), "r"(b0), "r"(b1));
}

// Y[128 x 576] = X[128 x K] @ Wp^T; cols 0..511 -> g_Ym (fp16), 512..575 -> g_Yroot (fp32)
__global__ void __launch_bounds__(256, 2) k_gemm_mma(const float* __restrict__ Xext,
                                                     int K, int useH) {
    extern __shared__ char smem[];
    const float* __restrict__ X = useH ? (const float*)g_h : Xext;
    const int RB = K * 2;
    const int OFF_AH = 0;
    const int OFF_AL = 128 * RB;
    const int OFF_BH = 256 * RB;
    const int OFF_BL = 320 * RB;
    uint32_t sb = smem_u32(smem);

    int tid = threadIdx.x, wid = tid >> 5, lane = tid & 31;
    int row0 = blockIdx.x * 128;
    int KQ = K >> 2;

    // ---- load A, split to bf16 hi/lo, swizzled store ----
    for (int q = tid; q < 128 * KQ; q += 256) {
        int row = q / KQ, k = (q % KQ) * 4;
        float4 v = make_float4(0.f, 0.f, 0.f, 0.f);
        int rg = row0 + row;
        if (rg < NNODES) v = *(const float4*)(X + (size_t)rg * K + k);
        __nv_bfloat16 h0 = __float2bfloat16(v.x), h1 = __float2bfloat16(v.y);
        __nv_bfloat16 h2 = __float2bfloat16(v.z), h3 = __float2bfloat16(v.w);
        __nv_bfloat16 l0 = __float2bfloat16(v.x - __bfloat162float(h0));
        __nv_bfloat16 l1 = __float2bfloat16(v.y - __bfloat162float(h1));
        __nv_bfloat16 l2 = __float2bfloat16(v.z - __bfloat162float(h2));
        __nv_bfloat16 l3 = __float2bfloat16(v.w - __bfloat162float(h3));
        uint2 hp, lp;
        hp.x = ((uint32_t)__bfloat16_as_ushort(h1) << 16) | __bfloat16_as_ushort(h0);
        hp.y = ((uint32_t)__bfloat16_as_ushort(h3) << 16) | __bfloat16_as_ushort(h2);
        lp.x = ((uint32_t)__bfloat16_as_ushort(l1) << 16) | __bfloat16_as_ushort(l0);
        lp.y = ((uint32_t)__bfloat16_as_ushort(l3) << 16) | __bfloat16_as_ushort(l2);
        int chunk = (k >> 3) ^ (row & 7);
        int off = row * RB + chunk * 16 + (k & 7) * 2;
        *(uint2*)(smem + OFF_AH + off) = hp;
        *(uint2*)(smem + OFF_AL + off) = lp;
    }
    __syncthreads();

    int wrow = (wid >> 1) * 32;
    int wcol = (wid & 1) * 32;
    int CPR = K >> 3;

    for (int nb = 0; nb < 9; nb++) {
        int col0 = nb * 64;
        for (int q = tid; q < 64 * CPR; q += 256) {
            int n = q / CPR, kc = q % CPR;
            size_t gsrc = (size_t)(col0 + n) * K + kc * 8;
            int off = n * RB + ((kc ^ (n & 7)) * 16);
            *(uint4*)(smem + OFF_BH + off) = *(const uint4*)(g_Wh + gsrc);
            *(uint4*)(smem + OFF_BL + off) = *(const uint4*)(g_Wl + gsrc);
        }
        __syncthreads();

        float acc[2][4][4];
#pragma unroll
        for (int mt = 0; mt < 2; mt++)
#pragma unroll
            for (int nt = 0; nt < 4; nt++)
#pragma unroll
                for (int j = 0; j < 4; j++) acc[mt][nt][j] = 0.f;

        int arow[2], as[2];
#pragma unroll
        for (int mt = 0; mt < 2; mt++) {
            int r = wrow + mt * 16 + (lane & 7) + ((lane >> 3) & 1) * 8;
            arow[mt] = r * RB;
            as[mt] = r & 7;
        }
        int akc = lane >> 4;
        int brow[2], bs[2];
#pragma unroll
        for (int nt2 = 0; nt2 < 2; nt2++) {
            int n = wcol + nt2 * 16 + (lane & 7) + (lane >> 4) * 8;
            brow[nt2] = n * RB;
            bs[nt2] = n & 7;
        }
        int bkc = (lane >> 3) & 1;

        int nkstep = K >> 4;
        for (int ks = 0; ks < nkstep; ks++) {
            int kc0 = ks * 2;
            uint32_t ah[2][4], al[2][4], bh[2][4], bl[2][4];
#pragma unroll
            for (int mt = 0; mt < 2; mt++) {
                uint32_t off = arow[mt] + (uint32_t)(((kc0 + akc) ^ as[mt]) * 16);
                ldm4(ah[mt], sb + OFF_AH + off);
                ldm4(al[mt], sb + OFF_AL + off);
            }
#pragma unroll
            for (int nt2 = 0; nt2 < 2; nt2++) {
                uint32_t off = brow[nt2] + (uint32_t)(((kc0 + bkc) ^ bs[nt2]) * 16);
                ldm4(bh[nt2], sb + OFF_BH + off);
                ldm4(bl[nt2], sb + OFF_BL + off);
            }
#pragma unroll
            for (int mt = 0; mt < 2; mt++) {
#pragma unroll
                for (int nt = 0; nt < 4; nt++) {
                    uint32_t b0h = bh[nt >> 1][(nt & 1) * 2], b1h = bh[nt >> 1][(nt & 1) * 2 + 1];
                    uint32_t b0l = bl[nt >> 1][(nt & 1) * 2], b1l = bl[nt >> 1][(nt & 1) * 2 + 1];
                    mma16816(acc[mt][nt], ah[mt], b0h, b1h);
                    mma16816(acc[mt][nt], ah[mt], b0l, b1l);
                    mma16816(acc[mt][nt], al[mt], b0h, b1h);
                }
            }
        }

        // ---- epilogue ----
        if (nb < 8) {
            // relation columns -> fp16 messages
#pragma unroll
            for (int mt = 0; mt < 2; mt++) {
                int r0 = row0 + wrow + mt * 16 + (lane >> 2);
#pragma unroll
                for (int nt = 0; nt < 4; nt++) {
                    int c = col0 + wcol + nt * 8 + (lane & 3) * 2;
                    if (r0 < NNODES)
                        *(__half2*)(g_Ym + (size_t)r0 * RELCOLS + c) =
                            __floats2half2_rn(acc[mt][nt][0], acc[mt][nt][1]);
                    if (r0 + 8 < NNODES)
                        *(__half2*)(g_Ym + (size_t)(r0 + 8) * RELCOLS + c) =
                            __floats2half2_rn(acc[mt][nt][2], acc[mt][nt][3]);
                }
            }
        } else {
            // root columns -> fp32
#pragma unroll
            for (int mt = 0; mt < 2; mt++) {
                int r0 = row0 + wrow + mt * 16 + (lane >> 2);
#pragma unroll
                for (int nt = 0; nt < 4; nt++) {
                    int c = wcol + nt * 8 + (lane & 3) * 2;   // 0..63 local
                    if (r0 < NNODES)
                        *(float2*)(g_Yroot + (size_t)r0 * HID + c) =
                            make_float2(acc[mt][nt][0], acc[mt][nt][1]);
                    if (r0 + 8 < NNODES)
                        *(float2*)(g_Yroot + (size_t)(r0 + 8) * HID + c) =
                            make_float2(acc[mt][nt][2], acc[mt][nt][3]);
                }
            }
        }
        __syncthreads();
    }
}

// ---------------- aggregation: warp per node, fp16 gather --------------------
__global__ void __launch_bounds__(256) k_agg(const float* __restrict__ bias,
                                             float* __restrict__ outext, int mode) {
    int warp = (blockIdx.x * blockDim.x + threadIdx.x) >> 5;
    int lane = threadIdx.x & 31;
    if (warp >= NNODES) return;
    float* __restrict__ out = mode ? (float*)g_h : outext;
    int start = g_rowptr[warp];
    int end   = g_rowptr[warp + 1];
    float ax = 0.f, ay = 0.f;
    int e = start;
    for (; e + 8 <= end; e += 8) {
        float2 v[8];
        float  s[8];
#pragma unroll
        for (int j = 0; j < 8; j++) {
            int2 m = g_emeta[e + j];
            v[j] = __half22float2(*((const __half2*)(g_Ym + m.x) + lane));
            s[j] = __int_as_float(m.y);
        }
#pragma unroll
        for (int j = 0; j < 8; j++) {
            ax = fmaf(v[j].x, s[j], ax);
            ay = fmaf(v[j].y, s[j], ay);
        }
    }
    for (; e < end; e++) {
        int2 m = g_emeta[e];
        float2 v = __half22float2(*((const __half2*)(g_Ym + m.x) + lane));
        float s = __int_as_float(m.y);
        ax = fmaf(v.x, s, ax); ay = fmaf(v.y, s, ay);
    }
    const float* base = g_Yroot + (size_t)warp * HID;
    float bx = ax + base[lane * 2 + 0] + bias[lane * 2 + 0];
    float by = ay + base[lane * 2 + 1] + bias[lane * 2 + 1];
    if (mode) { bx = fmaxf(bx, 0.f); by = fmaxf(by, 0.f); }
    *(float2*)(out + (size_t)warp * HID + lane * 2) = make_float2(bx, by);
}

// ---------------- launch ------------------------------------------------------
extern "C" void kernel_launch(void* const* d_in, const int* in_sizes, int n_in,
                              void* d_out, int out_size) {
    const float* x     = (const float*)d_in[0];
    const int*   ei    = (const int*)d_in[1];
    const int*   et    = (const int*)d_in[2];
    const float* W1    = (const float*)d_in[3];
    const float* root1 = (const float*)d_in[4];
    const float* b1    = (const float*)d_in[5];
    const float* W2    = (const float*)d_in[6];
    const float* root2 = (const float*)d_in[7];
    const float* b2    = (const float*)d_in[8];
    float* out = (float*)d_out;

    const int* src = ei;
    const int* dst = ei + NEDGES;

    cudaFuncSetAttribute(k_gemm_mma, cudaFuncAttributeMaxDynamicSharedMemorySize,
                         384 * CIN * 2);

    // CSR + degrees (shared by both layers)
    k_zero_cnt<<<(NREL * NNODES + 255) / 256, 256>>>();
    k_count<<<(NEDGES + 255) / 256, 256>>>(dst, et);
    int nb = (NNODES + 1023) / 1024;
    k_scan1<<<nb, 1024>>>();
    k_scan2<<<1, 32>>>(nb);
    k_scan3<<<(NNODES + 255) / 256, 256>>>();
    k_scatter<<<(NEDGES + 255) / 256, 256>>>(src, dst, et);

    int ggrid = (NNODES + 127) / 128;
    int agrid = (NNODES * 32 + 255) / 256;

    // layer 1
    k_pack<<<(CIN * YCOLS + 255) / 256, 256>>>(W1, root1, CIN);
    k_gemm_mma<<<ggrid, 256, 384 * CIN * 2>>>(x, CIN, 0);
    k_agg<<<agrid, 256>>>(b1, nullptr, 1);

    // layer 2
    k_pack<<<(HID * YCOLS + 255) / 256, 256>>>(W2, root2, HID);
    k_gemm_mma<<<ggrid, 256, 384 * HID * 2>>>(nullptr, HID, 1);
    k_agg<<<agrid, 256>>>(b2, out, 0);
}

// round 6
// speedup vs baseline: 2.0214x; 1.1169x over previous
#include <cuda_runtime.h>
#include <cuda_fp16.h>
#include <cstdint>

#define NNODES 100000
#define NEDGES 3200000
#define NREL   8
#define CIN    128
#define HID    64
#define RELCOLS 512
#define YCOLS (RELCOLS + HID)

// ---------------- scratch ----------------------------------------------------
__device__ __align__(16) __half g_Ym[(size_t)NNODES * RELCOLS];   // relation msgs fp16
__device__ __align__(16) float  g_Yroot[(size_t)NNODES * HID];    // root part fp32
__device__ __align__(16) float  g_h[(size_t)NNODES * HID];
__device__ __align__(16) __half g_Wh[YCOLS * CIN];   // weights fp16 hi, [col][k]
__device__ __align__(16) __half g_Wl[YCOLS * CIN];   // weights fp16 lo (residual)
__device__ int   g_cnt[NREL * NNODES];
__device__ int   g_rowptr[NNODES + 1];
__device__ int   g_cursor[NNODES];
__device__ int   g_bsums[256];
__device__ int2  g_emeta[NEDGES];

// ---------------- CSR build --------------------------------------------------
__global__ void k_zero_cnt() {
    int i = blockIdx.x * blockDim.x + threadIdx.x;
    if (i < NREL * NNODES) g_cnt[i] = 0;
}
__global__ void k_count(const int* __restrict__ dst, const int* __restrict__ et) {
    int e = blockIdx.x * blockDim.x + threadIdx.x;
    if (e < NEDGES) atomicAdd(&g_cnt[__ldcs(et + e) * NNODES + __ldcs(dst + e)], 1);
}
__global__ void k_scan1() {
    __shared__ int sh[1024];
    int d = blockIdx.x * 1024 + threadIdx.x;
    int tot = 0;
    if (d < NNODES) {
#pragma unroll
        for (int r = 0; r < NREL; r++) tot += g_cnt[r * NNODES + d];
    }
    sh[threadIdx.x] = tot;
    __syncthreads();
    for (int off = 1; off < 1024; off <<= 1) {
        int v = 0;
        if (threadIdx.x >= off) v = sh[threadIdx.x - off];
        __syncthreads();
        sh[threadIdx.x] += v;
        __syncthreads();
    }
    if (d < NNODES) g_rowptr[d] = sh[threadIdx.x] - tot;
    if (threadIdx.x == 1023) g_bsums[blockIdx.x] = sh[1023];
}
__global__ void k_scan2(int nb) {
    if (threadIdx.x == 0 && blockIdx.x == 0) {
        int run = 0;
        for (int i = 0; i < nb; i++) { int v = g_bsums[i]; g_bsums[i] = run; run += v; }
    }
}
__global__ void k_scan3() {
    int d = blockIdx.x * blockDim.x + threadIdx.x;
    if (d < NNODES) {
        int v = g_rowptr[d] + g_bsums[d >> 10];
        g_rowptr[d] = v;
        g_cursor[d] = v;
    }
    if (d == 0) g_rowptr[NNODES] = NEDGES;
}
__global__ void k_scatter(const int* __restrict__ src, const int* __restrict__ dst,
                          const int* __restrict__ et) {
    int e = blockIdx.x * blockDim.x + threadIdx.x;
    if (e >= NEDGES) return;
    int s = __ldcs(src + e), d = __ldcs(dst + e), r = __ldcs(et + e);
    int pos = atomicAdd(&g_cursor[d], 1);
    float sc = 1.0f / (float)g_cnt[r * NNODES + d];
    g_emeta[pos] = make_int2(s * RELCOLS + r * HID, __float_as_int(sc));
}

// ---------------- weight pack: fp16 hi/lo, [col][k] ---------------------------
__global__ void k_pack(const float* __restrict__ W, const float* __restrict__ root, int K) {
    int i = blockIdx.x * blockDim.x + threadIdx.x;
    if (i >= K * YCOLS) return;
    int j = i / K, k = i % K;
    float v;
    if (j < RELCOLS) {
        int r = j >> 6, h = j & 63;
        v = W[((size_t)r * K + k) * HID + h];
    } else {
        v = root[(size_t)k * HID + (j - RELCOLS)];
    }
    __half hi = __float2half_rn(v);
    g_Wh[i] = hi;
    g_Wl[i] = __float2half_rn(v - __half2float(hi));
}

// ---------------- mma.sync GEMM ----------------------------------------------
__device__ __forceinline__ uint32_t smem_u32(const void* p) {
    uint32_t a;
    asm("{ .reg .u64 t; cvta.to.shared.u64 t, %1; cvt.u32.u64 %0, t; }" : "=r"(a) : "l"(p));
    return a;
}
__device__ __forceinline__ void ldm4(uint32_t* r, uint32_t addr) {
    asm volatile("ldmatrix.sync.aligned.m8n8.x4.shared.b16 {%0,%1,%2,%3}, [%4];"
                 : "=r"(r[0]), "=r"(r[1]), "=r"(r[2]), "=r"(r[3]) : "r"(addr));
}
__device__ __forceinline__ void mma16816(float* d, const uint32_t* a, uint32_t b0, uint32_t b1) {
    asm volatile(
        "mma.sync.aligned.m16n8k16.row.col.f32.f16.f16.f32 "
        "{%0,%1,%2,%3}, {%4,%5,%6,%7}, {%8,%9}, {%0,%1,%2,%3};"
        : "+f"(d[0]), "+f"(d[1]), "+f"(d[2]), "+f"(d[3])
        : "r"(a[0]), "r"(a[1]), "r"(a[2]), "r"(a[3]), "r"(b0), "r"(b1));
}
__device__ __forceinline__ void cpa16(uint32_t saddr, const void* g) {
    asm volatile("cp.async.cg.shared.global [%0], [%1], 16;" :: "r"(saddr), "l"(g));
}
#define CP_COMMIT() asm volatile("cp.async.commit_group;" ::: "memory")
#define CP_WAIT0()  asm volatile("cp.async.wait_group 0;" ::: "memory")

// Y[128 x 576] = X[128 x K] @ W^T;  acc = Ah*(Bh + Bl), A fp16-rounded once.
__global__ void __launch_bounds__(256, 2) k_gemm_mma(const float* __restrict__ Xext,
                                                     int K, int useH) {
    extern __shared__ char smem[];
    const float* __restrict__ X = useH ? (const float*)g_h : Xext;
    const int RB = K * 2;                       // bytes per smem row
    const int OFF_A = 0;                        // 128*RB
    const int OFF_B0 = 128 * RB;                // 4 buffers of 64*RB: [buf][hi/lo]
    uint32_t sb = smem_u32(smem);

    int tid = threadIdx.x, wid = tid >> 5, lane = tid & 31;
    int row0 = blockIdx.x * 128;
    int KQ = K >> 2;
    int CPR = K >> 3;

    // prefetch B chunk nb into buffer buf (hi + lo)
    auto prefetch = [&](int nb, int buf) {
        int bh = OFF_B0 + (buf * 2 + 0) * 64 * RB;
        int bl = OFF_B0 + (buf * 2 + 1) * 64 * RB;
        int col0 = nb * 64;
        for (int q = tid; q < 64 * CPR; q += 256) {
            int n = q / CPR, kc = q % CPR;
            size_t gsrc = (size_t)(col0 + n) * K + kc * 8;
            int off = n * RB + ((kc ^ (n & 7)) * 16);
            cpa16(sb + bh + off, g_Wh + gsrc);
            cpa16(sb + bl + off, g_Wl + gsrc);
        }
        CP_COMMIT();
    };

    prefetch(0, 0);   // overlap B0 DMA with A convert

    // ---- load A (128 x K fp32), round to fp16, swizzled store ----
    for (int q = tid; q < 128 * KQ; q += 256) {
        int row = q / KQ, k = (q % KQ) * 4;
        float4 v = make_float4(0.f, 0.f, 0.f, 0.f);
        int rg = row0 + row;
        if (rg < NNODES) v = *(const float4*)(X + (size_t)rg * K + k);
        uint2 hp;
        __half2 p0 = __floats2half2_rn(v.x, v.y);
        __half2 p1 = __floats2half2_rn(v.z, v.w);
        hp.x = *(uint32_t*)&p0;
        hp.y = *(uint32_t*)&p1;
        int chunk = (k >> 3) ^ (row & 7);
        *(uint2*)(smem + OFF_A + row * RB + chunk * 16 + (k & 7) * 2) = hp;
    }
    CP_WAIT0();
    __syncthreads();

    int wrow = (wid >> 1) * 32;
    int wcol = (wid & 1) * 32;

    // per-lane ldmatrix bases
    int arow[2], as[2];
#pragma unroll
    for (int mt = 0; mt < 2; mt++) {
        int r = wrow + mt * 16 + (lane & 7) + ((lane >> 3) & 1) * 8;
        arow[mt] = r * RB;
        as[mt] = r & 7;
    }
    int akc = lane >> 4;
    int brow[2], bs[2];
#pragma unroll
    for (int nt2 = 0; nt2 < 2; nt2++) {
        int n = wcol + nt2 * 16 + (lane & 7) + (lane >> 4) * 8;
        brow[nt2] = n * RB;
        bs[nt2] = n & 7;
    }
    int bkc = (lane >> 3) & 1;
    int nkstep = K >> 4;

    for (int nb = 0; nb < 9; nb++) {
        int cur = nb & 1;
        if (nb < 8) prefetch(nb + 1, cur ^ 1);

        uint32_t bhB = sb + OFF_B0 + (cur * 2 + 0) * 64 * RB;
        uint32_t blB = sb + OFF_B0 + (cur * 2 + 1) * 64 * RB;

        float acc[2][4][4];
#pragma unroll
        for (int mt = 0; mt < 2; mt++)
#pragma unroll
            for (int nt = 0; nt < 4; nt++)
#pragma unroll
                for (int j = 0; j < 4; j++) acc[mt][nt][j] = 0.f;

        for (int ks = 0; ks < nkstep; ks++) {
            int kc0 = ks * 2;
            uint32_t ah[2][4], bh[2][4], bl[2][4];
#pragma unroll
            for (int mt = 0; mt < 2; mt++) {
                uint32_t off = arow[mt] + (uint32_t)(((kc0 + akc) ^ as[mt]) * 16);
                ldm4(ah[mt], sb + OFF_A + off);
            }
#pragma unroll
            for (int nt2 = 0; nt2 < 2; nt2++) {
                uint32_t off = brow[nt2] + (uint32_t)(((kc0 + bkc) ^ bs[nt2]) * 16);
                ldm4(bh[nt2], bhB + off);
                ldm4(bl[nt2], blB + off);
            }
#pragma unroll
            for (int mt = 0; mt < 2; mt++) {
#pragma unroll
                for (int nt = 0; nt < 4; nt++) {
                    uint32_t h0 = bh[nt >> 1][(nt & 1) * 2], h1 = bh[nt >> 1][(nt & 1) * 2 + 1];
                    uint32_t l0 = bl[nt >> 1][(nt & 1) * 2], l1 = bl[nt >> 1][(nt & 1) * 2 + 1];
                    mma16816(acc[mt][nt], ah[mt], h0, h1);
                    mma16816(acc[mt][nt], ah[mt], l0, l1);
                }
            }
        }

        // ---- epilogue ----
        int col0 = nb * 64;
        if (nb < 8) {
#pragma unroll
            for (int mt = 0; mt < 2; mt++) {
                int r0 = row0 + wrow + mt * 16 + (lane >> 2);
#pragma unroll
                for (int nt = 0; nt < 4; nt++) {
                    int c = col0 + wcol + nt * 8 + (lane & 3) * 2;
                    if (r0 < NNODES)
                        *(__half2*)(g_Ym + (size_t)r0 * RELCOLS + c) =
                            __floats2half2_rn(acc[mt][nt][0], acc[mt][nt][1]);
                    if (r0 + 8 < NNODES)
                        *(__half2*)(g_Ym + (size_t)(r0 + 8) * RELCOLS + c) =
                            __floats2half2_rn(acc[mt][nt][2], acc[mt][nt][3]);
                }
            }
        } else {
#pragma unroll
            for (int mt = 0; mt < 2; mt++) {
                int r0 = row0 + wrow + mt * 16 + (lane >> 2);
#pragma unroll
                for (int nt = 0; nt < 4; nt++) {
                    int c = wcol + nt * 8 + (lane & 3) * 2;
                    if (r0 < NNODES)
                        *(float2*)(g_Yroot + (size_t)r0 * HID + c) =
                            make_float2(acc[mt][nt][0], acc[mt][nt][1]);
                    if (r0 + 8 < NNODES)
                        *(float2*)(g_Yroot + (size_t)(r0 + 8) * HID + c) =
                            make_float2(acc[mt][nt][2], acc[mt][nt][3]);
                }
            }
        }
        if (nb < 8) {
            CP_WAIT0();
            __syncthreads();
        }
    }
}

// ---------------- aggregation: warp per node, fp16 gather --------------------
__global__ void __launch_bounds__(256) k_agg(const float* __restrict__ bias,
                                             float* __restrict__ outext, int mode) {
    int warp = (blockIdx.x * blockDim.x + threadIdx.x) >> 5;
    int lane = threadIdx.x & 31;
    if (warp >= NNODES) return;
    float* __restrict__ out = mode ? (float*)g_h : outext;
    int start = g_rowptr[warp];
    int end   = g_rowptr[warp + 1];
    float ax = 0.f, ay = 0.f;
    int e = start;
    for (; e + 8 <= end; e += 8) {
        float2 v[8];
        float  s[8];
#pragma unroll
        for (int j = 0; j < 8; j++) {
            int2 m = __ldcs(&g_emeta[e + j]);
            v[j] = __half22float2(*((const __half2*)(g_Ym + m.x) + lane));
            s[j] = __int_as_float(m.y);
        }
#pragma unroll
        for (int j = 0; j < 8; j++) {
            ax = fmaf(v[j].x, s[j], ax);
            ay = fmaf(v[j].y, s[j], ay);
        }
    }
    for (; e < end; e++) {
        int2 m = __ldcs(&g_emeta[e]);
        float2 v = __half22float2(*((const __half2*)(g_Ym + m.x) + lane));
        float s = __int_as_float(m.y);
        ax = fmaf(v.x, s, ax); ay = fmaf(v.y, s, ay);
    }
    const float* base = g_Yroot + (size_t)warp * HID;
    float bx = ax + base[lane * 2 + 0] + bias[lane * 2 + 0];
    float by = ay + base[lane * 2 + 1] + bias[lane * 2 + 1];
    if (mode) { bx = fmaxf(bx, 0.f); by = fmaxf(by, 0.f); }
    *(float2*)(out + (size_t)warp * HID + lane * 2) = make_float2(bx, by);
}

// ---------------- launch ------------------------------------------------------
extern "C" void kernel_launch(void* const* d_in, const int* in_sizes, int n_in,
                              void* d_out, int out_size) {
    const float* x     = (const float*)d_in[0];
    const int*   ei    = (const int*)d_in[1];
    const int*   et    = (const int*)d_in[2];
    const float* W1    = (const float*)d_in[3];
    const float* root1 = (const float*)d_in[4];
    const float* b1    = (const float*)d_in[5];
    const float* W2    = (const float*)d_in[6];
    const float* root2 = (const float*)d_in[7];
    const float* b2    = (const float*)d_in[8];
    float* out = (float*)d_out;

    const int* src = ei;
    const int* dst = ei + NEDGES;

    cudaFuncSetAttribute(k_gemm_mma, cudaFuncAttributeMaxDynamicSharedMemorySize,
                         384 * CIN * 2);

    // CSR + degrees (shared by both layers)
    k_zero_cnt<<<(NREL * NNODES + 255) / 256, 256>>>();
    k_count<<<(NEDGES + 255) / 256, 256>>>(dst, et);
    int nb = (NNODES + 1023) / 1024;
    k_scan1<<<nb, 1024>>>();
    k_scan2<<<1, 32>>>(nb);
    k_scan3<<<(NNODES + 255) / 256, 256>>>();
    k_scatter<<<(NEDGES + 255) / 256, 256>>>(src, dst, et);

    int ggrid = (NNODES + 127) / 128;
    int agrid = (NNODES * 32 + 255) / 256;

    // layer 1
    k_pack<<<(CIN * YCOLS + 255) / 256, 256>>>(W1, root1, CIN);
    k_gemm_mma<<<ggrid, 256, 384 * CIN * 2>>>(x, CIN, 0);
    k_agg<<<agrid, 256>>>(b1, nullptr, 1);

    // layer 2
    k_pack<<<(HID * YCOLS + 255) / 256, 256>>>(W2, root2, HID);
    k_gemm_mma<<<ggrid, 256, 384 * HID * 2>>>(nullptr, HID, 1);
    k_agg<<<agrid, 256>>>(b2, out, 0);
}

// round 7
// speedup vs baseline: 2.1336x; 1.0555x over previous
#include <cuda_runtime.h>
#include <cuda_fp16.h>
#include <cstdint>

#define NNODES 100000
#define NEDGES 3200000
#define NREL   8
#define CIN    128
#define HID    64
#define RELCOLS 512
#define YCOLS (RELCOLS + HID)

// ---------------- scratch ----------------------------------------------------
__device__ __align__(16) __half g_Ym[(size_t)NNODES * RELCOLS];   // relation msgs fp16
__device__ __align__(16) float  g_Yroot[(size_t)NNODES * HID];    // root part fp32
__device__ __align__(16) float  g_h[(size_t)NNODES * HID];
__device__ __align__(16) __half g_Wh[YCOLS * CIN];   // weights fp16 hi, [col][k]
__device__ __align__(16) __half g_Wl[YCOLS * CIN];   // weights fp16 lo (residual)
__device__ int   g_cnt[NREL * NNODES];
__device__ int   g_rowptr[NNODES + 1];
__device__ int   g_cursor[NNODES];
__device__ int   g_bsums[256];
__device__ int2  g_emeta[NEDGES];

// ---------------- CSR build --------------------------------------------------
__global__ void k_count(const int* __restrict__ dst, const int* __restrict__ et) {
    int e = blockIdx.x * blockDim.x + threadIdx.x;
    if (e < NEDGES) atomicAdd(&g_cnt[__ldcs(et + e) * NNODES + __ldcs(dst + e)], 1);
}
__global__ void k_scan1() {
    __shared__ int sh[1024];
    int d = blockIdx.x * 1024 + threadIdx.x;
    int tot = 0;
    if (d < NNODES) {
#pragma unroll
        for (int r = 0; r < NREL; r++) tot += g_cnt[r * NNODES + d];
    }
    sh[threadIdx.x] = tot;
    __syncthreads();
    for (int off = 1; off < 1024; off <<= 1) {
        int v = 0;
        if (threadIdx.x >= off) v = sh[threadIdx.x - off];
        __syncthreads();
        sh[threadIdx.x] += v;
        __syncthreads();
    }
    if (d < NNODES) g_rowptr[d] = sh[threadIdx.x] - tot;
    if (threadIdx.x == 1023) g_bsums[blockIdx.x] = sh[1023];
}
__global__ void k_scan2(int nb) {
    if (threadIdx.x == 0 && blockIdx.x == 0) {
        int run = 0;
        for (int i = 0; i < nb; i++) { int v = g_bsums[i]; g_bsums[i] = run; run += v; }
    }
}
__global__ void k_scan3() {
    int d = blockIdx.x * blockDim.x + threadIdx.x;
    if (d < NNODES) {
        int v = g_rowptr[d] + g_bsums[d >> 10];
        g_rowptr[d] = v;
        g_cursor[d] = v;
    }
    if (d == 0) g_rowptr[NNODES] = NEDGES;
}
__global__ void k_scatter(const int* __restrict__ src, const int* __restrict__ dst,
                          const int* __restrict__ et) {
    int e = blockIdx.x * blockDim.x + threadIdx.x;
    if (e >= NEDGES) return;
    int s = __ldcs(src + e), d = __ldcs(dst + e), r = __ldcs(et + e);
    int pos = atomicAdd(&g_cursor[d], 1);
    float sc = 1.0f / (float)g_cnt[r * NNODES + d];
    g_emeta[pos] = make_int2(s * RELCOLS + r * HID, __float_as_int(sc));
}

// ---------------- weight pack: fp16 hi/lo, [col][k] ---------------------------
__global__ void k_pack(const float* __restrict__ W, const float* __restrict__ root, int K) {
    int i = blockIdx.x * blockDim.x + threadIdx.x;
    if (i >= K * YCOLS) return;
    int j = i / K, k = i % K;
    float v;
    if (j < RELCOLS) {
        int r = j >> 6, h = j & 63;
        v = W[((size_t)r * K + k) * HID + h];
    } else {
        v = root[(size_t)k * HID + (j - RELCOLS)];
    }
    __half hi = __float2half_rn(v);
    g_Wh[i] = hi;
    g_Wl[i] = __float2half_rn(v - __half2float(hi));
}

// ---------------- mma.sync GEMM (unchanged from R5) ---------------------------
__device__ __forceinline__ uint32_t smem_u32(const void* p) {
    uint32_t a;
    asm("{ .reg .u64 t; cvta.to.shared.u64 t, %1; cvt.u32.u64 %0, t; }" : "=r"(a) : "l"(p));
    return a;
}
__device__ __forceinline__ void ldm4(uint32_t* r, uint32_t addr) {
    asm volatile("ldmatrix.sync.aligned.m8n8.x4.shared.b16 {%0,%1,%2,%3}, [%4];"
                 : "=r"(r[0]), "=r"(r[1]), "=r"(r[2]), "=r"(r[3]) : "r"(addr));
}
__device__ __forceinline__ void mma16816(float* d, const uint32_t* a, uint32_t b0, uint32_t b1) {
    asm volatile(
        "mma.sync.aligned.m16n8k16.row.col.f32.f16.f16.f32 "
        "{%0,%1,%2,%3}, {%4,%5,%6,%7}, {%8,%9}, {%0,%1,%2,%3};"
        : "+f"(d[0]), "+f"(d[1]), "+f"(d[2]), "+f"(d[3])
        : "r"(a[0]), "r"(a[1]), "r"(a[2]), "r"(a[3]), "r"(b0), "r"(b1));
}
__device__ __forceinline__ void cpa16(uint32_t saddr, const void* g) {
    asm volatile("cp.async.cg.shared.global [%0], [%1], 16;" :: "r"(saddr), "l"(g));
}
#define CP_COMMIT() asm volatile("cp.async.commit_group;" ::: "memory")
#define CP_WAIT0()  asm volatile("cp.async.wait_group 0;" ::: "memory")

__global__ void __launch_bounds__(256, 2) k_gemm_mma(const float* __restrict__ Xext,
                                                     int K, int useH) {
    extern __shared__ char smem[];
    const float* __restrict__ X = useH ? (const float*)g_h : Xext;
    const int RB = K * 2;
    const int OFF_A = 0;
    const int OFF_B0 = 128 * RB;
    uint32_t sb = smem_u32(smem);

    int tid = threadIdx.x, wid = tid >> 5, lane = tid & 31;
    int row0 = blockIdx.x * 128;
    int KQ = K >> 2;
    int CPR = K >> 3;

    auto prefetch = [&](int nb, int buf) {
        int bh = OFF_B0 + (buf * 2 + 0) * 64 * RB;
        int bl = OFF_B0 + (buf * 2 + 1) * 64 * RB;
        int col0 = nb * 64;
        for (int q = tid; q < 64 * CPR; q += 256) {
            int n = q / CPR, kc = q % CPR;
            size_t gsrc = (size_t)(col0 + n) * K + kc * 8;
            int off = n * RB + ((kc ^ (n & 7)) * 16);
            cpa16(sb + bh + off, g_Wh + gsrc);
            cpa16(sb + bl + off, g_Wl + gsrc);
        }
        CP_COMMIT();
    };

    prefetch(0, 0);

    for (int q = tid; q < 128 * KQ; q += 256) {
        int row = q / KQ, k = (q % KQ) * 4;
        float4 v = make_float4(0.f, 0.f, 0.f, 0.f);
        int rg = row0 + row;
        if (rg < NNODES) v = *(const float4*)(X + (size_t)rg * K + k);
        uint2 hp;
        __half2 p0 = __floats2half2_rn(v.x, v.y);
        __half2 p1 = __floats2half2_rn(v.z, v.w);
        hp.x = *(uint32_t*)&p0;
        hp.y = *(uint32_t*)&p1;
        int chunk = (k >> 3) ^ (row & 7);
        *(uint2*)(smem + OFF_A + row * RB + chunk * 16 + (k & 7) * 2) = hp;
    }
    CP_WAIT0();
    __syncthreads();

    int wrow = (wid >> 1) * 32;
    int wcol = (wid & 1) * 32;

    int arow[2], as[2];
#pragma unroll
    for (int mt = 0; mt < 2; mt++) {
        int r = wrow + mt * 16 + (lane & 7) + ((lane >> 3) & 1) * 8;
        arow[mt] = r * RB;
        as[mt] = r & 7;
    }
    int akc = lane >> 4;
    int brow[2], bs[2];
#pragma unroll
    for (int nt2 = 0; nt2 < 2; nt2++) {
        int n = wcol + nt2 * 16 + (lane & 7) + (lane >> 4) * 8;
        brow[nt2] = n * RB;
        bs[nt2] = n & 7;
    }
    int bkc = (lane >> 3) & 1;
    int nkstep = K >> 4;

    for (int nb = 0; nb < 9; nb++) {
        int cur = nb & 1;
        if (nb < 8) prefetch(nb + 1, cur ^ 1);

        uint32_t bhB = sb + OFF_B0 + (cur * 2 + 0) * 64 * RB;
        uint32_t blB = sb + OFF_B0 + (cur * 2 + 1) * 64 * RB;

        float acc[2][4][4];
#pragma unroll
        for (int mt = 0; mt < 2; mt++)
#pragma unroll
            for (int nt = 0; nt < 4; nt++)
#pragma unroll
                for (int j = 0; j < 4; j++) acc[mt][nt][j] = 0.f;

        for (int ks = 0; ks < nkstep; ks++) {
            int kc0 = ks * 2;
            uint32_t ah[2][4], bh[2][4], bl[2][4];
#pragma unroll
            for (int mt = 0; mt < 2; mt++) {
                uint32_t off = arow[mt] + (uint32_t)(((kc0 + akc) ^ as[mt]) * 16);
                ldm4(ah[mt], sb + OFF_A + off);
            }
#pragma unroll
            for (int nt2 = 0; nt2 < 2; nt2++) {
                uint32_t off = brow[nt2] + (uint32_t)(((kc0 + bkc) ^ bs[nt2]) * 16);
                ldm4(bh[nt2], bhB + off);
                ldm4(bl[nt2], blB + off);
            }
#pragma unroll
            for (int mt = 0; mt < 2; mt++) {
#pragma unroll
                for (int nt = 0; nt < 4; nt++) {
                    uint32_t h0 = bh[nt >> 1][(nt & 1) * 2], h1 = bh[nt >> 1][(nt & 1) * 2 + 1];
                    uint32_t l0 = bl[nt >> 1][(nt & 1) * 2], l1 = bl[nt >> 1][(nt & 1) * 2 + 1];
                    mma16816(acc[mt][nt], ah[mt], h0, h1);
                    mma16816(acc[mt][nt], ah[mt], l0, l1);
                }
            }
        }

        int col0 = nb * 64;
        if (nb < 8) {
#pragma unroll
            for (int mt = 0; mt < 2; mt++) {
                int r0 = row0 + wrow + mt * 16 + (lane >> 2);
#pragma unroll
                for (int nt = 0; nt < 4; nt++) {
                    int c = col0 + wcol + nt * 8 + (lane & 3) * 2;
                    if (r0 < NNODES)
                        *(__half2*)(g_Ym + (size_t)r0 * RELCOLS + c) =
                            __floats2half2_rn(acc[mt][nt][0], acc[mt][nt][1]);
                    if (r0 + 8 < NNODES)
                        *(__half2*)(g_Ym + (size_t)(r0 + 8) * RELCOLS + c) =
                            __floats2half2_rn(acc[mt][nt][2], acc[mt][nt][3]);
                }
            }
        } else {
#pragma unroll
            for (int mt = 0; mt < 2; mt++) {
                int r0 = row0 + wrow + mt * 16 + (lane >> 2);
#pragma unroll
                for (int nt = 0; nt < 4; nt++) {
                    int c = wcol + nt * 8 + (lane & 3) * 2;
                    if (r0 < NNODES)
                        *(float2*)(g_Yroot + (size_t)r0 * HID + c) =
                            make_float2(acc[mt][nt][0], acc[mt][nt][1]);
                    if (r0 + 8 < NNODES)
                        *(float2*)(g_Yroot + (size_t)(r0 + 8) * HID + c) =
                            make_float2(acc[mt][nt][2], acc[mt][nt][3]);
                }
            }
        }
        if (nb < 8) {
            CP_WAIT0();
            __syncthreads();
        }
    }
}

// ---------------- aggregation: warp per node, 4 edges per warp-load ----------
// lane = (grp = lane>>3, sub = lane&7). Lane loads 16B (8 halves) of edge e+grp,
// covering message halves [sub*8, sub*8+8). Cross-grp combine via 2 shfl_xor.
__global__ void __launch_bounds__(256) k_agg(const float* __restrict__ bias,
                                             float* __restrict__ outext, int mode) {
    int warp = (blockIdx.x * blockDim.x + threadIdx.x) >> 5;
    int lane = threadIdx.x & 31;
    if (warp >= NNODES) return;
    float* __restrict__ out = mode ? (float*)g_h : outext;

    int grp = lane >> 3;
    int sub = lane & 7;
    int start = g_rowptr[warp];
    int end   = g_rowptr[warp + 1];

    float acc[8];
#pragma unroll
    for (int j = 0; j < 8; j++) acc[j] = 0.f;

    int e = start;
    // main loop: two full 4-edge packs per iteration
    for (; e + 8 <= end; e += 8) {
        int2 m0 = __ldcs(&g_emeta[e + grp]);
        int2 m1 = __ldcs(&g_emeta[e + 4 + grp]);
        uint4 r0 = *(const uint4*)(g_Ym + m0.x + sub * 8);
        uint4 r1 = *(const uint4*)(g_Ym + m1.x + sub * 8);
        float s0 = __int_as_float(m0.y);
        float s1 = __int_as_float(m1.y);
        const __half2* h0 = (const __half2*)&r0;
        const __half2* h1 = (const __half2*)&r1;
#pragma unroll
        for (int j = 0; j < 4; j++) {
            float2 f0 = __half22float2(h0[j]);
            float2 f1 = __half22float2(h1[j]);
            acc[j * 2 + 0] = fmaf(f0.x, s0, acc[j * 2 + 0]);
            acc[j * 2 + 1] = fmaf(f0.y, s0, acc[j * 2 + 1]);
            acc[j * 2 + 0] = fmaf(f1.x, s1, acc[j * 2 + 0]);
            acc[j * 2 + 1] = fmaf(f1.y, s1, acc[j * 2 + 1]);
        }
    }
    // tail: predicated 4-edge packs
    for (; e < end; e += 4) {
        int ei = e + grp;
        int ec = ei < end ? ei : e;           // e is valid (e < end here)
        int2 m = __ldcs(&g_emeta[ec]);
        float s = (ei < end) ? __int_as_float(m.y) : 0.f;
        uint4 r = *(const uint4*)(g_Ym + m.x + sub * 8);
        const __half2* h = (const __half2*)&r;
#pragma unroll
        for (int j = 0; j < 4; j++) {
            float2 f = __half22float2(h[j]);
            acc[j * 2 + 0] = fmaf(f.x, s, acc[j * 2 + 0]);
            acc[j * 2 + 1] = fmaf(f.y, s, acc[j * 2 + 1]);
        }
    }

    // combine the 4 edge-groups
#pragma unroll
    for (int j = 0; j < 8; j++) {
        acc[j] += __shfl_xor_sync(0xFFFFFFFFu, acc[j], 8);
        acc[j] += __shfl_xor_sync(0xFFFFFFFFu, acc[j], 16);
    }

    if (grp == 0) {
        const float* rootp = g_Yroot + (size_t)warp * HID + sub * 8;
        float4 rv0 = *(const float4*)(rootp + 0);
        float4 rv1 = *(const float4*)(rootp + 4);
        float4 bv0 = *(const float4*)(bias + sub * 8 + 0);
        float4 bv1 = *(const float4*)(bias + sub * 8 + 4);
        float4 o0, o1;
        o0.x = acc[0] + rv0.x + bv0.x; o0.y = acc[1] + rv0.y + bv0.y;
        o0.z = acc[2] + rv0.z + bv0.z; o0.w = acc[3] + rv0.w + bv0.w;
        o1.x = acc[4] + rv1.x + bv1.x; o1.y = acc[5] + rv1.y + bv1.y;
        o1.z = acc[6] + rv1.z + bv1.z; o1.w = acc[7] + rv1.w + bv1.w;
        if (mode) {
            o0.x = fmaxf(o0.x, 0.f); o0.y = fmaxf(o0.y, 0.f);
            o0.z = fmaxf(o0.z, 0.f); o0.w = fmaxf(o0.w, 0.f);
            o1.x = fmaxf(o1.x, 0.f); o1.y = fmaxf(o1.y, 0.f);
            o1.z = fmaxf(o1.z, 0.f); o1.w = fmaxf(o1.w, 0.f);
        }
        float* op = out + (size_t)warp * HID + sub * 8;
        *(float4*)(op + 0) = o0;
        *(float4*)(op + 4) = o1;
    }
}

// ---------------- launch ------------------------------------------------------
extern "C" void kernel_launch(void* const* d_in, const int* in_sizes, int n_in,
                              void* d_out, int out_size) {
    const float* x     = (const float*)d_in[0];
    const int*   ei    = (const int*)d_in[1];
    const int*   et    = (const int*)d_in[2];
    const float* W1    = (const float*)d_in[3];
    const float* root1 = (const float*)d_in[4];
    const float* b1    = (const float*)d_in[5];
    const float* W2    = (const float*)d_in[6];
    const float* root2 = (const float*)d_in[7];
    const float* b2    = (const float*)d_in[8];
    float* out = (float*)d_out;

    const int* src = ei;
    const int* dst = ei + NEDGES;

    cudaFuncSetAttribute(k_gemm_mma, cudaFuncAttributeMaxDynamicSharedMemorySize,
                         384 * CIN * 2);

    // CSR + degrees (shared by both layers)
    void* cnt_ptr = nullptr;
    cudaGetSymbolAddress(&cnt_ptr, g_cnt);
    cudaMemsetAsync(cnt_ptr, 0, sizeof(int) * NREL * NNODES);
    k_count<<<(NEDGES + 255) / 256, 256>>>(dst, et);
    int nb = (NNODES + 1023) / 1024;
    k_scan1<<<nb, 1024>>>();
    k_scan2<<<1, 32>>>(nb);
    k_scan3<<<(NNODES + 255) / 256, 256>>>();
    k_scatter<<<(NEDGES + 255) / 256, 256>>>(src, dst, et);

    int ggrid = (NNODES + 127) / 128;
    int agrid = (NNODES * 32 + 255) / 256;

    // layer 1
    k_pack<<<(CIN * YCOLS + 255) / 256, 256>>>(W1, root1, CIN);
    k_gemm_mma<<<ggrid, 256, 384 * CIN * 2>>>(x, CIN, 0);
    k_agg<<<agrid, 256>>>(b1, nullptr, 1);

    // layer 2
    k_pack<<<(HID * YCOLS + 255) / 256, 256>>>(W2, root2, HID);
    k_gemm_mma<<<ggrid, 256, 384 * HID * 2>>>(nullptr, HID, 1);
    k_agg<<<agrid, 256>>>(b2, out, 0);
}

// round 8
// speedup vs baseline: 2.1793x; 1.0214x over previous
#include <cuda_runtime.h>
#include <cuda_fp16.h>
#include <cstdint>

#define NNODES 100000
#define NEDGES 3200000
#define NREL   8
#define CIN    128
#define HID    64
#define RELCOLS 512
#define YCOLS (RELCOLS + HID)

// ---------------- scratch ----------------------------------------------------
__device__ __align__(16) __half g_Ym[(size_t)NNODES * RELCOLS];   // relation msgs fp16
__device__ __align__(16) float  g_Yroot[(size_t)NNODES * HID];    // root part fp32
__device__ __align__(16) float  g_h[(size_t)NNODES * HID];
__device__ __align__(16) __half g_Wh[YCOLS * CIN];   // weights fp16 hi, [col][k]
__device__ __align__(16) __half g_Wl[YCOLS * CIN];   // weights fp16 lo (residual)
__device__ int   g_cnt[NREL * NNODES];
__device__ int   g_rowptr[NNODES + 1];
__device__ int   g_cursor[NNODES];
__device__ int   g_bsums[256];
__device__ int2  g_emeta[NEDGES];

// ---------------- CSR build --------------------------------------------------
__global__ void k_count(const int* __restrict__ dst, const int* __restrict__ et) {
    int e = blockIdx.x * blockDim.x + threadIdx.x;
    if (e < NEDGES) atomicAdd(&g_cnt[__ldcs(et + e) * NNODES + __ldcs(dst + e)], 1);
}
__global__ void k_scan1() {
    __shared__ int sh[1024];
    int d = blockIdx.x * 1024 + threadIdx.x;
    int tot = 0;
    if (d < NNODES) {
#pragma unroll
        for (int r = 0; r < NREL; r++) tot += g_cnt[r * NNODES + d];
    }
    sh[threadIdx.x] = tot;
    __syncthreads();
    for (int off = 1; off < 1024; off <<= 1) {
        int v = 0;
        if (threadIdx.x >= off) v = sh[threadIdx.x - off];
        __syncthreads();
        sh[threadIdx.x] += v;
        __syncthreads();
    }
    if (d < NNODES) g_rowptr[d] = sh[threadIdx.x] - tot;
    if (threadIdx.x == 1023) g_bsums[blockIdx.x] = sh[1023];
}
__global__ void k_scan2(int nb) {
    if (threadIdx.x == 0 && blockIdx.x == 0) {
        int run = 0;
        for (int i = 0; i < nb; i++) { int v = g_bsums[i]; g_bsums[i] = run; run += v; }
    }
}
__global__ void k_scan3() {
    int d = blockIdx.x * blockDim.x + threadIdx.x;
    if (d < NNODES) {
        int v = g_rowptr[d] + g_bsums[d >> 10];
        g_rowptr[d] = v;
        g_cursor[d] = v;
    }
    if (d == 0) g_rowptr[NNODES] = NEDGES;
}
__global__ void k_scatter(const int* __restrict__ src, const int* __restrict__ dst,
                          const int* __restrict__ et) {
    int e = blockIdx.x * blockDim.x + threadIdx.x;
    if (e >= NEDGES) return;
    int s = __ldcs(src + e), d = __ldcs(dst + e), r = __ldcs(et + e);
    int pos = atomicAdd(&g_cursor[d], 1);
    float sc = 1.0f / (float)g_cnt[r * NNODES + d];
    g_emeta[pos] = make_int2(s * RELCOLS + r * HID, __float_as_int(sc));
}

// ---------------- weight pack: fp16 hi/lo, [col][k] ---------------------------
__global__ void k_pack(const float* __restrict__ W, const float* __restrict__ root, int K) {
    int i = blockIdx.x * blockDim.x + threadIdx.x;
    if (i >= K * YCOLS) return;
    int j = i / K, k = i % K;
    float v;
    if (j < RELCOLS) {
        int r = j >> 6, h = j & 63;
        v = W[((size_t)r * K + k) * HID + h];
    } else {
        v = root[(size_t)k * HID + (j - RELCOLS)];
    }
    __half hi = __float2half_rn(v);
    g_Wh[i] = hi;
    g_Wl[i] = __float2half_rn(v - __half2float(hi));
}

// ---------------- mma.sync GEMM ----------------------------------------------
__device__ __forceinline__ uint32_t smem_u32(const void* p) {
    uint32_t a;
    asm("{ .reg .u64 t; cvta.to.shared.u64 t, %1; cvt.u32.u64 %0, t; }" : "=r"(a) : "l"(p));
    return a;
}
__device__ __forceinline__ void ldm4(uint32_t* r, uint32_t addr) {
    asm volatile("ldmatrix.sync.aligned.m8n8.x4.shared.b16 {%0,%1,%2,%3}, [%4];"
                 : "=r"(r[0]), "=r"(r[1]), "=r"(r[2]), "=r"(r[3]) : "r"(addr));
}
__device__ __forceinline__ void mma16816(float* d, const uint32_t* a, uint32_t b0, uint32_t b1) {
    asm volatile(
        "mma.sync.aligned.m16n8k16.row.col.f32.f16.f16.f32 "
        "{%0,%1,%2,%3}, {%4,%5,%6,%7}, {%8,%9}, {%0,%1,%2,%3};"
        : "+f"(d[0]), "+f"(d[1]), "+f"(d[2]), "+f"(d[3])
        : "r"(a[0]), "r"(a[1]), "r"(a[2]), "r"(a[3]), "r"(b0), "r"(b1));
}
__device__ __forceinline__ void cpa16(uint32_t saddr, const void* g) {
    asm volatile("cp.async.cg.shared.global [%0], [%1], 16;" :: "r"(saddr), "l"(g));
}
#define CP_COMMIT() asm volatile("cp.async.commit_group;" ::: "memory")
#define CP_WAIT0()  asm volatile("cp.async.wait_group 0;" ::: "memory")

__global__ void __launch_bounds__(256, 2) k_gemm_mma(const float* __restrict__ Xext,
                                                     int K, int useH) {
    extern __shared__ char smem[];
    const float* __restrict__ X = useH ? (const float*)g_h : Xext;
    const int RB = K * 2;
    const int OFF_A = 0;
    const int OFF_B0 = 128 * RB;
    uint32_t sb = smem_u32(smem);

    int tid = threadIdx.x, wid = tid >> 5, lane = tid & 31;
    int row0 = blockIdx.x * 128;
    int KQ = K >> 2;
    int CPR = K >> 3;

    auto prefetch = [&](int nb, int buf) {
        int bh = OFF_B0 + (buf * 2 + 0) * 64 * RB;
        int bl = OFF_B0 + (buf * 2 + 1) * 64 * RB;
        int col0 = nb * 64;
        for (int q = tid; q < 64 * CPR; q += 256) {
            int n = q / CPR, kc = q % CPR;
            size_t gsrc = (size_t)(col0 + n) * K + kc * 8;
            int off = n * RB + ((kc ^ (n & 7)) * 16);
            cpa16(sb + bh + off, g_Wh + gsrc);
            cpa16(sb + bl + off, g_Wl + gsrc);
        }
        CP_COMMIT();
    };

    prefetch(0, 0);

    for (int q = tid; q < 128 * KQ; q += 256) {
        int row = q / KQ, k = (q % KQ) * 4;
        float4 v = make_float4(0.f, 0.f, 0.f, 0.f);
        int rg = row0 + row;
        if (rg < NNODES) v = *(const float4*)(X + (size_t)rg * K + k);
        uint2 hp;
        __half2 p0 = __floats2half2_rn(v.x, v.y);
        __half2 p1 = __floats2half2_rn(v.z, v.w);
        hp.x = *(uint32_t*)&p0;
        hp.y = *(uint32_t*)&p1;
        int chunk = (k >> 3) ^ (row & 7);
        *(uint2*)(smem + OFF_A + row * RB + chunk * 16 + (k & 7) * 2) = hp;
    }
    CP_WAIT0();
    __syncthreads();

    int wrow = (wid >> 1) * 32;
    int wcol = (wid & 1) * 32;

    int arow[2], as[2];
#pragma unroll
    for (int mt = 0; mt < 2; mt++) {
        int r = wrow + mt * 16 + (lane & 7) + ((lane >> 3) & 1) * 8;
        arow[mt] = r * RB;
        as[mt] = r & 7;
    }
    int akc = lane >> 4;
    int brow[2], bs[2];
#pragma unroll
    for (int nt2 = 0; nt2 < 2; nt2++) {
        int n = wcol + nt2 * 16 + (lane & 7) + (lane >> 4) * 8;
        brow[nt2] = n * RB;
        bs[nt2] = n & 7;
    }
    int bkc = (lane >> 3) & 1;
    int nkstep = K >> 4;

    for (int nb = 0; nb < 9; nb++) {
        int cur = nb & 1;
        if (nb < 8) prefetch(nb + 1, cur ^ 1);

        uint32_t bhB = sb + OFF_B0 + (cur * 2 + 0) * 64 * RB;
        uint32_t blB = sb + OFF_B0 + (cur * 2 + 1) * 64 * RB;

        float acc[2][4][4];
#pragma unroll
        for (int mt = 0; mt < 2; mt++)
#pragma unroll
            for (int nt = 0; nt < 4; nt++)
#pragma unroll
                for (int j = 0; j < 4; j++) acc[mt][nt][j] = 0.f;

        for (int ks = 0; ks < nkstep; ks++) {
            int kc0 = ks * 2;
            uint32_t ah[2][4], bh[2][4], bl[2][4];
#pragma unroll
            for (int mt = 0; mt < 2; mt++) {
                uint32_t off = arow[mt] + (uint32_t)(((kc0 + akc) ^ as[mt]) * 16);
                ldm4(ah[mt], sb + OFF_A + off);
            }
#pragma unroll
            for (int nt2 = 0; nt2 < 2; nt2++) {
                uint32_t off = brow[nt2] + (uint32_t)(((kc0 + bkc) ^ bs[nt2]) * 16);
                ldm4(bh[nt2], bhB + off);
                ldm4(bl[nt2], blB + off);
            }
#pragma unroll
            for (int mt = 0; mt < 2; mt++) {
#pragma unroll
                for (int nt = 0; nt < 4; nt++) {
                    uint32_t h0 = bh[nt >> 1][(nt & 1) * 2], h1 = bh[nt >> 1][(nt & 1) * 2 + 1];
                    uint32_t l0 = bl[nt >> 1][(nt & 1) * 2], l1 = bl[nt >> 1][(nt & 1) * 2 + 1];
                    mma16816(acc[mt][nt], ah[mt], h0, h1);
                    mma16816(acc[mt][nt], ah[mt], l0, l1);
                }
            }
        }

        int col0 = nb * 64;
        if (nb < 8) {
#pragma unroll
            for (int mt = 0; mt < 2; mt++) {
                int r0 = row0 + wrow + mt * 16 + (lane >> 2);
#pragma unroll
                for (int nt = 0; nt < 4; nt++) {
                    int c = col0 + wcol + nt * 8 + (lane & 3) * 2;
                    if (r0 < NNODES)
                        *(__half2*)(g_Ym + (size_t)r0 * RELCOLS + c) =
                            __floats2half2_rn(acc[mt][nt][0], acc[mt][nt][1]);
                    if (r0 + 8 < NNODES)
                        *(__half2*)(g_Ym + (size_t)(r0 + 8) * RELCOLS + c) =
                            __floats2half2_rn(acc[mt][nt][2], acc[mt][nt][3]);
                }
            }
        } else {
#pragma unroll
            for (int mt = 0; mt < 2; mt++) {
                int r0 = row0 + wrow + mt * 16 + (lane >> 2);
#pragma unroll
                for (int nt = 0; nt < 4; nt++) {
                    int c = wcol + nt * 8 + (lane & 3) * 2;
                    if (r0 < NNODES)
                        *(float2*)(g_Yroot + (size_t)r0 * HID + c) =
                            make_float2(acc[mt][nt][0], acc[mt][nt][1]);
                    if (r0 + 8 < NNODES)
                        *(float2*)(g_Yroot + (size_t)(r0 + 8) * HID + c) =
                            make_float2(acc[mt][nt][2], acc[mt][nt][3]);
                }
            }
        }
        if (nb < 8) {
            CP_WAIT0();
            __syncthreads();
        }
    }
}

// ---------------- aggregation: warp per node, 4 edges per warp-load ----------
__global__ void __launch_bounds__(256) k_agg(const float* __restrict__ bias,
                                             float* __restrict__ outext, int mode) {
    int warp = (blockIdx.x * blockDim.x + threadIdx.x) >> 5;
    int lane = threadIdx.x & 31;
    if (warp >= NNODES) return;
    float* __restrict__ out = mode ? (float*)g_h : outext;

    int grp = lane >> 3;
    int sub = lane & 7;
    int start = g_rowptr[warp];
    int end   = g_rowptr[warp + 1];

    float acc[8];
#pragma unroll
    for (int j = 0; j < 8; j++) acc[j] = 0.f;

    int e = start;
    // main loop: four 4-edge packs in flight (16 edges / iter)
    for (; e + 16 <= end; e += 16) {
        int2 m0 = __ldcs(&g_emeta[e + grp]);
        int2 m1 = __ldcs(&g_emeta[e + 4 + grp]);
        int2 m2 = __ldcs(&g_emeta[e + 8 + grp]);
        int2 m3 = __ldcs(&g_emeta[e + 12 + grp]);
        uint4 r0 = *(const uint4*)(g_Ym + m0.x + sub * 8);
        uint4 r1 = *(const uint4*)(g_Ym + m1.x + sub * 8);
        uint4 r2 = *(const uint4*)(g_Ym + m2.x + sub * 8);
        uint4 r3 = *(const uint4*)(g_Ym + m3.x + sub * 8);
        float s0 = __int_as_float(m0.y), s1 = __int_as_float(m1.y);
        float s2 = __int_as_float(m2.y), s3 = __int_as_float(m3.y);
        const __half2* h0 = (const __half2*)&r0;
        const __half2* h1 = (const __half2*)&r1;
        const __half2* h2 = (const __half2*)&r2;
        const __half2* h3 = (const __half2*)&r3;
#pragma unroll
        for (int j = 0; j < 4; j++) {
            float2 f0 = __half22float2(h0[j]);
            float2 f1 = __half22float2(h1[j]);
            float2 f2 = __half22float2(h2[j]);
            float2 f3 = __half22float2(h3[j]);
            acc[j * 2 + 0] = fmaf(f0.x, s0, acc[j * 2 + 0]);
            acc[j * 2 + 1] = fmaf(f0.y, s0, acc[j * 2 + 1]);
            acc[j * 2 + 0] = fmaf(f1.x, s1, acc[j * 2 + 0]);
            acc[j * 2 + 1] = fmaf(f1.y, s1, acc[j * 2 + 1]);
            acc[j * 2 + 0] = fmaf(f2.x, s2, acc[j * 2 + 0]);
            acc[j * 2 + 1] = fmaf(f2.y, s2, acc[j * 2 + 1]);
            acc[j * 2 + 0] = fmaf(f3.x, s3, acc[j * 2 + 0]);
            acc[j * 2 + 1] = fmaf(f3.y, s3, acc[j * 2 + 1]);
        }
    }
    // tail: predicated 4-edge packs
    for (; e < end; e += 4) {
        int ei = e + grp;
        int ec = ei < end ? ei : e;
        int2 m = __ldcs(&g_emeta[ec]);
        float s = (ei < end) ? __int_as_float(m.y) : 0.f;
        uint4 r = *(const uint4*)(g_Ym + m.x + sub * 8);
        const __half2* h = (const __half2*)&r;
#pragma unroll
        for (int j = 0; j < 4; j++) {
            float2 f = __half22float2(h[j]);
            acc[j * 2 + 0] = fmaf(f.x, s, acc[j * 2 + 0]);
            acc[j * 2 + 1] = fmaf(f.y, s, acc[j * 2 + 1]);
        }
    }

#pragma unroll
    for (int j = 0; j < 8; j++) {
        acc[j] += __shfl_xor_sync(0xFFFFFFFFu, acc[j], 8);
        acc[j] += __shfl_xor_sync(0xFFFFFFFFu, acc[j], 16);
    }

    if (grp == 0) {
        const float* rootp = g_Yroot + (size_t)warp * HID + sub * 8;
        float4 rv0 = *(const float4*)(rootp + 0);
        float4 rv1 = *(const float4*)(rootp + 4);
        float4 bv0 = *(const float4*)(bias + sub * 8 + 0);
        float4 bv1 = *(const float4*)(bias + sub * 8 + 4);
        float4 o0, o1;
        o0.x = acc[0] + rv0.x + bv0.x; o0.y = acc[1] + rv0.y + bv0.y;
        o0.z = acc[2] + rv0.z + bv0.z; o0.w = acc[3] + rv0.w + bv0.w;
        o1.x = acc[4] + rv1.x + bv1.x; o1.y = acc[5] + rv1.y + bv1.y;
        o1.z = acc[6] + rv1.z + bv1.z; o1.w = acc[7] + rv1.w + bv1.w;
        if (mode) {
            o0.x = fmaxf(o0.x, 0.f); o0.y = fmaxf(o0.y, 0.f);
            o0.z = fmaxf(o0.z, 0.f); o0.w = fmaxf(o0.w, 0.f);
            o1.x = fmaxf(o1.x, 0.f); o1.y = fmaxf(o1.y, 0.f);
            o1.z = fmaxf(o1.z, 0.f); o1.w = fmaxf(o1.w, 0.f);
        }
        float* op = out + (size_t)warp * HID + sub * 8;
        *(float4*)(op + 0) = o0;
        *(float4*)(op + 4) = o1;
    }
}

// ---------------- launch ------------------------------------------------------
extern "C" void kernel_launch(void* const* d_in, const int* in_sizes, int n_in,
                              void* d_out, int out_size) {
    const float* x     = (const float*)d_in[0];
    const int*   ei    = (const int*)d_in[1];
    const int*   et    = (const int*)d_in[2];
    const float* W1    = (const float*)d_in[3];
    const float* root1 = (const float*)d_in[4];
    const float* b1    = (const float*)d_in[5];
    const float* W2    = (const float*)d_in[6];
    const float* root2 = (const float*)d_in[7];
    const float* b2    = (const float*)d_in[8];
    float* out = (float*)d_out;

    const int* src = ei;
    const int* dst = ei + NEDGES;

    static cudaStream_t s1 = nullptr;
    static cudaEvent_t ev_fork = nullptr, ev_csr = nullptr;
    static void* cnt_ptr = nullptr;
    if (!s1) {
        cudaStreamCreateWithFlags(&s1, cudaStreamNonBlocking);
        cudaEventCreateWithFlags(&ev_fork, cudaEventDisableTiming);
        cudaEventCreateWithFlags(&ev_csr, cudaEventDisableTiming);
        cudaGetSymbolAddress(&cnt_ptr, g_cnt);
        cudaFuncSetAttribute(k_gemm_mma, cudaFuncAttributeMaxDynamicSharedMemorySize,
                             384 * CIN * 2);
    }

    // ---- fork: CSR build on side stream, overlapped with pack1+gemm1 ----
    cudaEventRecord(ev_fork, 0);
    cudaStreamWaitEvent(s1, ev_fork, 0);

    cudaMemsetAsync(cnt_ptr, 0, sizeof(int) * NREL * NNODES, s1);
    k_count<<<(NEDGES + 255) / 256, 256, 0, s1>>>(dst, et);
    int nb = (NNODES + 1023) / 1024;
    k_scan1<<<nb, 1024, 0, s1>>>();
    k_scan2<<<1, 32, 0, s1>>>(nb);
    k_scan3<<<(NNODES + 255) / 256, 256, 0, s1>>>();
    k_scatter<<<(NEDGES + 255) / 256, 256, 0, s1>>>(src, dst, et);
    cudaEventRecord(ev_csr, s1);

    int ggrid = (NNODES + 127) / 128;
    int agrid = (NNODES * 32 + 255) / 256;

    // main stream: layer-1 transform runs concurrent with CSR build
    k_pack<<<(CIN * YCOLS + 255) / 256, 256>>>(W1, root1, CIN);
    k_gemm_mma<<<ggrid, 256, 384 * CIN * 2>>>(x, CIN, 0);

    // ---- join: agg1 needs both GEMM1 output and CSR ----
    cudaStreamWaitEvent(0, ev_csr, 0);
    k_agg<<<agrid, 256>>>(b1, nullptr, 1);

    // layer 2
    k_pack<<<(HID * YCOLS + 255) / 256, 256>>>(W2, root2, HID);
    k_gemm_mma<<<ggrid, 256, 384 * HID * 2>>>(nullptr, HID, 1);
    k_agg<<<agrid, 256>>>(b2, out, 0);
}